// round 5
// baseline (speedup 1.0000x reference)
#include <cuda_runtime.h>
#include <cstdint>

// Problem constants
#define NB 8
#define NW 32
#define NX 64
#define NY 64
#define NT 40
#define NKZ 8          // retained T modes (M3)
#define NK 24          // retained X/Y modes (2*M1 = 2*M2)
#define XYT 163840     // 64*64*40
#define YTD 2560       // 64*40
#define NMODE 4608     // 24*24*8
#define WPL 4718592    // 4*32*32*12*12*8  (spectral weights per layer)

// ---- scratch (device globals; no allocations anywhere) ----
static __device__ float  g_bufA[(size_t)NB*NW*XYT];                 // 168 MB
static __device__ float  g_bufB[(size_t)NB*NW*XYT];                 // 168 MB
static __device__ float2 g_ft1[(size_t)NB*NW*NX*NY*NKZ];            // 67 MB
static __device__ float2 g_ft2[(size_t)NB*NW*NX*NK*NKZ];            // 25 MB
static __device__ float2 g_modes [(size_t)NB*NW*NMODE];             // 9.4 MB
static __device__ float2 g_modes2[(size_t)NB*NW*NMODE];             // 9.4 MB
static __device__ float2 g_wt[(size_t)3*WPL];                       // 113 MB (transposed spectral weights)
static __device__ float2 g_tw_t[NKZ*NT];    // forward T twiddles  e^{-2pi i k t/40}
static __device__ float2 g_itw_t[NKZ*NT];   // inverse T twiddles  c_k/(XYT) * e^{+2pi i k t/40}
static __device__ float2 g_tw_yx[NK*64];    // forward X/Y twiddles e^{-2pi i kv y/64}

__device__ __forceinline__ void cfma(float2& a, float2 b, float2 c){
  a.x = fmaf(b.x, c.x, fmaf(-b.y, c.y, a.x));
  a.y = fmaf(b.x, c.y, fmaf( b.y, c.x, a.y));
}
__device__ __forceinline__ void cfma_cj(float2& a, float2 b, float2 c){ // a += b*conj(c)
  a.x = fmaf(b.x, c.x, fmaf( b.y, c.y, a.x));
  a.y = fmaf(b.y, c.x, fmaf(-b.x, c.y, a.y));
}
__device__ __forceinline__ float gelu_f(float z){
  return 0.5f*z*(1.0f + erff(z*0.7071067811865476f));
}

// ---- twiddle tables ----
__global__ void k_init_tw(){
  int tid = threadIdx.x;
  for (int i = tid; i < NKZ*NT; i += blockDim.x){
    int k = i / NT, t = i % NT;
    float s, c; sincospif(-(float)(k*t)/20.0f, &s, &c);   // -2pi k t / 40
    g_tw_t[i] = make_float2(c, s);
    float sc = ((k==0) ? 1.0f : 2.0f) * (1.0f/163840.0f);
    float s2, c2; sincospif((float)(k*t)/20.0f, &s2, &c2);
    g_itw_t[i] = make_float2(sc*c2, sc*s2);
  }
  for (int i = tid; i < NK*64; i += blockDim.x){
    int j = i / 64, y = i % 64;
    int kv = (j < 12) ? j : j + 40;                        // 0..11, 52..63
    float s, c; sincospif(-(float)(kv*y)/32.0f, &s, &c);   // -2pi kv y / 64
    g_tw_yx[i] = make_float2(c, s);
  }
}

// ---- transpose spectral weights [r][io][mloc] -> [mode][io] via 32x32 shared tile ----
__global__ void __launch_bounds__(256) k_prep_w_t(const float* __restrict__ wr,
                                                  const float* __restrict__ wi, int L){
  __shared__ float2 s[32][33];
  int m0  = blockIdx.x * 32;     // 36 tiles over mloc (1152)
  int io0 = blockIdx.y * 32;     // 32 tiles over io (1024)
  int r   = blockIdx.z;
  int tid = threadIdx.x;
  {
    int mt = tid & 31, iot0 = tid >> 5;
    const size_t inbase = (size_t)r * 1024 * 1152;
    #pragma unroll
    for (int u = 0; u < 4; u++){
      int io = io0 + iot0 + u*8;
      size_t off = inbase + (size_t)io*1152 + m0 + mt;
      s[iot0 + u*8][mt] = make_float2(wr[off], wi[off]);
    }
  }
  __syncthreads();
  {
    int iot = tid & 31, mt0 = tid >> 5;
    int rbase = (r & 1) * 2304 + ((r >> 1) & 1) * 96;
    float2* dst = g_wt + (size_t)L*WPL;
    #pragma unroll
    for (int u = 0; u < 4; u++){
      int m  = m0 + mt0 + u*8;
      int m1 = m / 96, rem = m % 96;
      int mode = rbase + m1*192 + rem;
      dst[(size_t)mode*1024 + io0 + iot] = s[iot][mt0 + u*8];
    }
  }
}

// ---- fc0: lift [B,X,Y,T,5] -> v [B,W,X,Y,T] ----
__global__ void k_fc0(const float* __restrict__ h, const float* __restrict__ xin,
                      const float* __restrict__ w, const float* __restrict__ b){
  int p = blockIdx.x * blockDim.x + threadIdx.x;
  if (p >= NB*XYT) return;
  int bb = p / XYT, rem = p % XYT;
  float in5[5];
  in5[0] = h[(size_t)p*2];   in5[1] = h[(size_t)p*2+1];
  in5[2] = xin[(size_t)p*3]; in5[3] = xin[(size_t)p*3+1]; in5[4] = xin[(size_t)p*3+2];
  float* o = g_bufA + (size_t)bb*NW*XYT + rem;
  #pragma unroll 4
  for (int c = 0; c < NW; c++){
    float v = b[c];
    #pragma unroll
    for (int f = 0; f < 5; f++) v = fmaf(in5[f], w[f*NW + c], v);
    o[(size_t)c*XYT] = v;
  }
}

// ---- forward partial DFT over T: v[b,c,x,y,t] -> ft1[b,c,x,y,k] ----
__global__ void k_fwdT(int dir){
  __shared__ float  s[NY*41];
  __shared__ float2 stw[NKZ*NT];
  const float* vin = dir ? g_bufB : g_bufA;
  int bcx = blockIdx.x;                       // (b*W+c)*64 + x
  const float* src = vin + (size_t)bcx*YTD;
  for (int i = threadIdx.x; i < YTD; i += 64) s[(i/NT)*41 + (i%NT)] = src[i];
  for (int i = threadIdx.x; i < NKZ*NT; i += 64) stw[i] = g_tw_t[i];
  __syncthreads();
  int y = threadIdx.x;
  float2 acc[NKZ];
  #pragma unroll
  for (int k = 0; k < NKZ; k++) acc[k] = make_float2(0.f, 0.f);
  for (int t = 0; t < NT; t++){
    float vv = s[y*41 + t];
    #pragma unroll
    for (int k = 0; k < NKZ; k++){
      float2 tw = stw[k*NT + t];
      acc[k].x = fmaf(vv, tw.x, acc[k].x);
      acc[k].y = fmaf(vv, tw.y, acc[k].y);
    }
  }
  float2* dst = g_ft1 + ((size_t)bcx*NY + y)*NKZ;
  #pragma unroll
  for (int k = 0; k < NKZ; k++) dst[k] = acc[k];
}

// ---- forward partial DFT over Y: ft1[b,c,x,y,k] -> ft2[b,c,x,j2,k] ----
__global__ void k_fwdY(){
  __shared__ float2 sv[NY*NKZ];     // 4 KB
  __shared__ float2 stw[NK*64];     // 12 KB
  int bcx = blockIdx.x;
  for (int i = threadIdx.x; i < NY*NKZ; i += 192) sv[i] = g_ft1[(size_t)bcx*512 + i];
  for (int i = threadIdx.x; i < NK*64; i += 192) stw[i] = g_tw_yx[i];
  __syncthreads();
  int j = threadIdx.x >> 3, k = threadIdx.x & 7;
  float2 acc = make_float2(0.f, 0.f);
  for (int y = 0; y < 64; y++) cfma(acc, sv[y*8 + k], stw[j*64 + y]);
  g_ft2[(size_t)bcx*192 + threadIdx.x] = acc;
}

// ---- forward partial DFT over X: ft2[b,c,x,j2,k] -> modes[b,c,j1,j2,k] ----
__global__ void k_fwdX(){
  __shared__ float2 stw[64];
  int bc = blockIdx.x / NK, j1 = blockIdx.x % NK;
  if (threadIdx.x < 64) stw[threadIdx.x] = g_tw_yx[j1*64 + threadIdx.x];
  __syncthreads();
  const float2* src = g_ft2 + (size_t)bc*NX*192 + threadIdx.x;
  float2 acc = make_float2(0.f, 0.f);
  for (int x = 0; x < 64; x++) cfma(acc, src[(size_t)x*192], stw[x]);
  g_modes[(size_t)bc*NMODE + j1*192 + threadIdx.x] = acc;
}

// ---- channel mix per mode ----
__global__ void k_mix(int L){
  __shared__ float2 s_in[256];
  __shared__ float2 s_w[1024];
  int m = blockIdx.x;
  int tid = threadIdx.x;
  s_in[tid] = g_modes[(size_t)tid*NMODE + m];
  const float2* wt = g_wt + (size_t)L*WPL + (size_t)m*1024;
  for (int i = tid; i < 1024; i += 256) s_w[i] = wt[i];
  __syncthreads();
  int bb = tid >> 5, o = tid & 31;
  float2 acc = make_float2(0.f, 0.f);
  #pragma unroll 8
  for (int i = 0; i < 32; i++) cfma(acc, s_in[bb*32 + i], s_w[i*32 + o]);
  g_modes2[(size_t)(bb*32 + o)*NMODE + m] = acc;
}

// ---- inverse over X ----
__global__ void k_invX(){
  __shared__ float2 stw[NK*64];     // 12 KB
  int bo = blockIdx.x;
  int tid = threadIdx.x;            // j2*8+k, 192 threads
  for (int i = tid; i < NK*64; i += 192) stw[i] = g_tw_yx[i];
  float2 m[NK];
  #pragma unroll
  for (int j1 = 0; j1 < NK; j1++)
    m[j1] = g_modes2[(size_t)bo*NMODE + j1*192 + tid];
  __syncthreads();
  for (int x = 0; x < 64; x++){
    float2 acc = make_float2(0.f, 0.f);
    #pragma unroll
    for (int j1 = 0; j1 < NK; j1++) cfma_cj(acc, m[j1], stw[j1*64 + x]);
    g_ft2[((size_t)bo*64 + x)*192 + tid] = acc;
  }
}

// ---- inverse over Y ----
__global__ void k_invY(){
  __shared__ float2 s_in[192];
  __shared__ float2 stw[NK*64];
  int box = blockIdx.x;
  if (threadIdx.x < 192) s_in[threadIdx.x] = g_ft2[(size_t)box*192 + threadIdx.x];
  for (int i = threadIdx.x; i < NK*64; i += 256) stw[i] = g_tw_yx[i];
  __syncthreads();
  for (int o = threadIdx.x; o < 512; o += 256){
    int y = o >> 3, k = o & 7;
    float2 acc = make_float2(0.f, 0.f);
    #pragma unroll 8
    for (int j2 = 0; j2 < NK; j2++) cfma_cj(acc, s_in[j2*8 + k], stw[j2*64 + y]);
    g_ft1[(size_t)box*512 + o] = acc;
  }
}

// ---- inverse over T (+scale+Re) + conv1x1 + bias + optional gelu ----
// Register-blocked: 2 xy per block; each thread owns a 2-o x 5-t output tile.
__global__ void __launch_bounds__(256) k_invT_pw(int dir, const float* __restrict__ convw,
                          const float* __restrict__ convb, int act){
  __shared__ float  s_v[2*32*40];      // 10.0 KB (input v, reused for output)
  __shared__ float  s_w[32*33];        // padded stride to avoid o-indexed conflicts
  __shared__ float2 s_h[2*32*9];       // padded
  __shared__ float2 s_itw[NKZ*NT];
  __shared__ float  s_b[NW];
  const float* vin  = dir ? g_bufB : g_bufA;
  float*       vout = dir ? g_bufA : g_bufB;
  int gx  = blockIdx.x;                // xy-pair index
  int bb  = gx >> 11;                  // 2048 pairs per batch
  int xy0 = (gx & 2047) * 2;
  int tid = threadIdx.x;
  size_t base = (size_t)(bb*32)*XYT + (size_t)xy0*NT;    // + c*XYT

  for (int idx = tid; idx < 640; idx += 256){
    int c = idx / 20, m = idx % 20;
    float4 v4 = *(const float4*)(vin + base + (size_t)c*XYT + m*4);
    int hh = m / 10, mm = m % 10;
    *(float4*)&s_v[hh*1280 + c*40 + mm*4] = v4;
  }
  for (int idx = tid; idx < 512; idx += 256){
    int hh = idx >> 8, rem = idx & 255, o = rem >> 3, k = rem & 7;
    s_h[hh*288 + o*9 + k] = g_ft1[(size_t)(bb*32+o)*32768 + (size_t)(xy0+hh)*8 + k];
  }
  for (int i = tid; i < 1024; i += 256) s_w[(i>>5)*33 + (i&31)] = convw[i];
  for (int i = tid; i < NKZ*NT; i += 256) s_itw[i] = g_itw_t[i];
  if (tid < NW) s_b[tid] = convb[tid];
  __syncthreads();

  int half = tid >> 7, r = tid & 127;
  int o0 = (r >> 3) * 2, t0 = (r & 7) * 5;
  float acc0[5], acc1[5];
  {
    float b0 = s_b[o0], b1 = s_b[o0+1];
    #pragma unroll
    for (int j = 0; j < 5; j++){ acc0[j] = b0; acc1[j] = b1; }
  }
  {
    float2 h0[8], h1[8];
    #pragma unroll
    for (int k = 0; k < 8; k++){
      h0[k] = s_h[half*288 + o0*9 + k];
      h1[k] = s_h[half*288 + (o0+1)*9 + k];
    }
    #pragma unroll
    for (int k = 0; k < 8; k++){
      #pragma unroll
      for (int j = 0; j < 5; j++){
        float2 tw = s_itw[k*NT + t0 + j];
        acc0[j] = fmaf(h0[k].x, tw.x, fmaf(-h0[k].y, tw.y, acc0[j]));
        acc1[j] = fmaf(h1[k].x, tw.x, fmaf(-h1[k].y, tw.y, acc1[j]));
      }
    }
  }
  {
    float w0[32], w1[32];
    #pragma unroll
    for (int i = 0; i < 32; i++){ w0[i] = s_w[o0*33 + i]; w1[i] = s_w[(o0+1)*33 + i]; }
    const float* vh = s_v + half*1280;
    #pragma unroll 8
    for (int i = 0; i < 32; i++){
      float vj[5];
      #pragma unroll
      for (int j = 0; j < 5; j++) vj[j] = vh[i*40 + t0 + j];
      #pragma unroll
      for (int j = 0; j < 5; j++){
        acc0[j] = fmaf(w0[i], vj[j], acc0[j]);
        acc1[j] = fmaf(w1[i], vj[j], acc1[j]);
      }
    }
  }
  if (act){
    #pragma unroll
    for (int j = 0; j < 5; j++){ acc0[j] = gelu_f(acc0[j]); acc1[j] = gelu_f(acc1[j]); }
  }
  __syncthreads();
  {
    float* ov = s_v + half*1280;
    #pragma unroll
    for (int j = 0; j < 5; j++){ ov[o0*40 + t0 + j] = acc0[j]; ov[(o0+1)*40 + t0 + j] = acc1[j]; }
  }
  __syncthreads();
  for (int idx = tid; idx < 640; idx += 256){
    int c = idx / 20, m = idx % 20;
    int hh = m / 10, mm = m % 10;
    float4 v4 = *(const float4*)&s_v[hh*1280 + c*40 + mm*4];
    *(float4*)(vout + base + (size_t)c*XYT + m*4) = v4;
  }
}

// ---- head: fc1 (gelu) + fc2; v in float4 registers (4 t per thread), w1 broadcast ----
__global__ void __launch_bounds__(256) k_head(const float* __restrict__ w1, const float* __restrict__ b1,
                       const float* __restrict__ w2, const float* __restrict__ b2,
                       float* __restrict__ out){
  __shared__ float s_w1[2048];
  __shared__ float s_b1[64];
  __shared__ float s_w2[128];
  __shared__ float s_b2[2];
  int tid = threadIdx.x;
  for (int i = tid; i < 2048; i += 256) s_w1[i] = w1[i];
  if (tid < 64)  s_b1[tid] = b1[tid];
  if (tid < 128) s_w2[tid] = w2[tid];
  if (tid < 2)   s_b2[tid] = b2[tid];
  __syncthreads();
  if (tid >= 240) return;
  int col = tid / 10, tp = tid % 10;         // thread covers t = 4*tp .. 4*tp+3
  int g = blockIdx.x * 24 + col;
  if (g >= 32768) return;
  int bb = g >> 12, xy = g & 4095;
  float4 vreg[32];
  const float* vb = g_bufB + (size_t)(bb*32)*XYT + (size_t)xy*NT + tp*4;
  #pragma unroll
  for (int c = 0; c < 32; c++) vreg[c] = *(const float4*)(vb + (size_t)c*XYT);
  float a0x = s_b2[0], a0y = s_b2[0], a0z = s_b2[0], a0w = s_b2[0];
  float a1x = s_b2[1], a1y = s_b2[1], a1z = s_b2[1], a1w = s_b2[1];
  for (int j = 0; j < 64; j++){
    float bj = s_b1[j];
    float hx = bj, hy = bj, hz = bj, hw = bj;
    #pragma unroll 8
    for (int c = 0; c < 32; c++){
      float w = s_w1[c*64 + j];
      hx = fmaf(vreg[c].x, w, hx);
      hy = fmaf(vreg[c].y, w, hy);
      hz = fmaf(vreg[c].z, w, hz);
      hw = fmaf(vreg[c].w, w, hw);
    }
    float gx = gelu_f(hx), gy = gelu_f(hy), gz = gelu_f(hz), gw = gelu_f(hw);
    float wa = s_w2[j*2], wb = s_w2[j*2 + 1];
    a0x = fmaf(gx, wa, a0x); a1x = fmaf(gx, wb, a1x);
    a0y = fmaf(gy, wa, a0y); a1y = fmaf(gy, wb, a1y);
    a0z = fmaf(gz, wa, a0z); a1z = fmaf(gz, wb, a1z);
    a0w = fmaf(gw, wa, a0w); a1w = fmaf(gw, wb, a1w);
  }
  float4 r0 = make_float4(a0x, a1x, a0y, a1y);
  float4 r1 = make_float4(a0z, a1z, a0w, a1w);
  float* op = out + (size_t)g*80 + tp*8;
  *(float4*)(op)     = r0;
  *(float4*)(op + 4) = r1;
}

static void run_layer(int L, int dir, int act, const float* convw, const float* convb){
  k_fwdT<<<NB*NW*NX, 64>>>(dir);
  k_fwdY<<<NB*NW*NX, 192>>>();
  k_fwdX<<<NB*NW*NK, 192>>>();
  k_mix<<<NMODE, 256>>>(L);
  k_invX<<<NB*NW, 192>>>();
  k_invY<<<NB*NW*NX, 256>>>();
  k_invT_pw<<<NB*2048, 256>>>(dir, convw, convb, act);
}

extern "C" void kernel_launch(void* const* d_in, const int* in_sizes, int n_in,
                              void* d_out, int out_size){
  (void)in_sizes; (void)n_in; (void)out_size;
  const float* h     = (const float*)d_in[0];
  const float* xin   = (const float*)d_in[1];
  const float* fc0_w = (const float*)d_in[2];
  const float* fc0_b = (const float*)d_in[3];
  const float* scr[3] = {(const float*)d_in[4], (const float*)d_in[6], (const float*)d_in[8]};
  const float* sci[3] = {(const float*)d_in[5], (const float*)d_in[7], (const float*)d_in[9]};
  const float* cw[3]  = {(const float*)d_in[10], (const float*)d_in[12], (const float*)d_in[14]};
  const float* cb[3]  = {(const float*)d_in[11], (const float*)d_in[13], (const float*)d_in[15]};
  const float* fc1_w = (const float*)d_in[16];
  const float* fc1_b = (const float*)d_in[17];
  const float* fc2_w = (const float*)d_in[18];
  const float* fc2_b = (const float*)d_in[19];
  float* out = (float*)d_out;

  k_init_tw<<<1, 256>>>();
  dim3 pgrid(36, 32, 4);
  for (int L = 0; L < 3; L++)
    k_prep_w_t<<<pgrid, 256>>>(scr[L], sci[L], L);
  k_fc0<<<(NB*XYT)/256, 256>>>(h, xin, fc0_w, fc0_b);

  run_layer(0, 0, 1, cw[0], cb[0]);   // A -> B, gelu
  run_layer(1, 1, 1, cw[1], cb[1]);   // B -> A, gelu
  run_layer(2, 0, 0, cw[2], cb[2]);   // A -> B, no act

  k_head<<<(32768 + 23)/24, 256>>>(fc1_w, fc1_b, fc2_w, fc2_b, out);
}

// round 6
// speedup vs baseline: 1.3517x; 1.3517x over previous
#include <cuda_runtime.h>
#include <cstdint>

// Problem constants
#define NB 8
#define NW 32
#define NX 64
#define NY 64
#define NT 40
#define NKZ 8          // retained T modes (M3)
#define NK 24          // retained X/Y modes (2*M1 = 2*M2)
#define XYT 163840     // 64*64*40
#define YTD 2560       // 64*40
#define NMODE 4608     // 24*24*8
#define WPL 4718592    // 4*32*32*12*12*8  (spectral weights per layer)

// ---- scratch (device globals; no allocations anywhere) ----
static __device__ float  g_bufA[(size_t)NB*NW*XYT];                 // 168 MB
static __device__ float  g_bufB[(size_t)NB*NW*XYT];                 // 168 MB
static __device__ float2 g_ft1[(size_t)NB*NW*NX*NY*NKZ];            // 67 MB
static __device__ float2 g_ft2[(size_t)NB*NW*NX*NK*NKZ];            // 25 MB
static __device__ float2 g_modes [(size_t)NB*NW*NMODE];             // 9.4 MB
static __device__ float2 g_modes2[(size_t)NB*NW*NMODE];             // 9.4 MB
static __device__ float2 g_wt[(size_t)3*WPL];                       // 113 MB (transposed spectral weights)
static __device__ float2 g_tw_t[NKZ*NT];    // forward T twiddles  e^{-2pi i k t/40}
static __device__ float2 g_itw_t[NKZ*NT];   // inverse T twiddles  c_k/(XYT) * e^{+2pi i k t/40}
static __device__ float2 g_tw_yx[NK*64];    // forward X/Y twiddles e^{-2pi i kv y/64}

__device__ __forceinline__ void cfma(float2& a, float2 b, float2 c){
  a.x = fmaf(b.x, c.x, fmaf(-b.y, c.y, a.x));
  a.y = fmaf(b.x, c.y, fmaf( b.y, c.x, a.y));
}
__device__ __forceinline__ void cfma_cj(float2& a, float2 b, float2 c){ // a += b*conj(c)
  a.x = fmaf(b.x, c.x, fmaf( b.y, c.y, a.x));
  a.y = fmaf(b.y, c.x, fmaf(-b.x, c.y, a.y));
}
__device__ __forceinline__ float gelu_f(float z){
  return 0.5f*z*(1.0f + erff(z*0.7071067811865476f));
}

// ---- twiddle tables ----
__global__ void k_init_tw(){
  int tid = threadIdx.x;
  for (int i = tid; i < NKZ*NT; i += blockDim.x){
    int k = i / NT, t = i % NT;
    float s, c; sincospif(-(float)(k*t)/20.0f, &s, &c);   // -2pi k t / 40
    g_tw_t[i] = make_float2(c, s);
    float sc = ((k==0) ? 1.0f : 2.0f) * (1.0f/163840.0f);
    float s2, c2; sincospif((float)(k*t)/20.0f, &s2, &c2);
    g_itw_t[i] = make_float2(sc*c2, sc*s2);
  }
  for (int i = tid; i < NK*64; i += blockDim.x){
    int j = i / 64, y = i % 64;
    int kv = (j < 12) ? j : j + 40;                        // 0..11, 52..63
    float s, c; sincospif(-(float)(kv*y)/32.0f, &s, &c);   // -2pi kv y / 64
    g_tw_yx[i] = make_float2(c, s);
  }
}

// ---- transpose spectral weights [r][io][mloc] -> [mode][io] via 32x32 shared tile ----
__global__ void __launch_bounds__(256) k_prep_w_t(const float* __restrict__ wr,
                                                  const float* __restrict__ wi, int L){
  __shared__ float2 s[32][33];
  int m0  = blockIdx.x * 32;     // 36 tiles over mloc (1152)
  int io0 = blockIdx.y * 32;     // 32 tiles over io (1024)
  int r   = blockIdx.z;
  int tid = threadIdx.x;
  {
    int mt = tid & 31, iot0 = tid >> 5;
    const size_t inbase = (size_t)r * 1024 * 1152;
    #pragma unroll
    for (int u = 0; u < 4; u++){
      int io = io0 + iot0 + u*8;
      size_t off = inbase + (size_t)io*1152 + m0 + mt;
      s[iot0 + u*8][mt] = make_float2(wr[off], wi[off]);
    }
  }
  __syncthreads();
  {
    int iot = tid & 31, mt0 = tid >> 5;
    int rbase = (r & 1) * 2304 + ((r >> 1) & 1) * 96;
    float2* dst = g_wt + (size_t)L*WPL;
    #pragma unroll
    for (int u = 0; u < 4; u++){
      int m  = m0 + mt0 + u*8;
      int m1 = m / 96, rem = m % 96;
      int mode = rbase + m1*192 + rem;
      dst[(size_t)mode*1024 + io0 + iot] = s[iot][mt0 + u*8];
    }
  }
}

// ---- fc0: lift [B,X,Y,T,5] -> v [B,W,X,Y,T] ----
__global__ void k_fc0(const float* __restrict__ h, const float* __restrict__ xin,
                      const float* __restrict__ w, const float* __restrict__ b){
  int p = blockIdx.x * blockDim.x + threadIdx.x;
  if (p >= NB*XYT) return;
  int bb = p / XYT, rem = p % XYT;
  float in5[5];
  in5[0] = h[(size_t)p*2];   in5[1] = h[(size_t)p*2+1];
  in5[2] = xin[(size_t)p*3]; in5[3] = xin[(size_t)p*3+1]; in5[4] = xin[(size_t)p*3+2];
  float* o = g_bufA + (size_t)bb*NW*XYT + rem;
  #pragma unroll 4
  for (int c = 0; c < NW; c++){
    float v = b[c];
    #pragma unroll
    for (int f = 0; f < 5; f++) v = fmaf(in5[f], w[f*NW + c], v);
    o[(size_t)c*XYT] = v;
  }
}

// ---- forward partial DFT over T: v[b,c,x,y,t] -> ft1[b,c,x,y,k] ----
__global__ void k_fwdT(int dir){
  __shared__ float  s[NY*41];
  __shared__ float2 stw[NKZ*NT];
  const float* vin = dir ? g_bufB : g_bufA;
  int bcx = blockIdx.x;                       // (b*W+c)*64 + x
  const float* src = vin + (size_t)bcx*YTD;
  for (int i = threadIdx.x; i < YTD; i += 64) s[(i/NT)*41 + (i%NT)] = src[i];
  for (int i = threadIdx.x; i < NKZ*NT; i += 64) stw[i] = g_tw_t[i];
  __syncthreads();
  int y = threadIdx.x;
  float2 acc[NKZ];
  #pragma unroll
  for (int k = 0; k < NKZ; k++) acc[k] = make_float2(0.f, 0.f);
  for (int t = 0; t < NT; t++){
    float vv = s[y*41 + t];
    #pragma unroll
    for (int k = 0; k < NKZ; k++){
      float2 tw = stw[k*NT + t];
      acc[k].x = fmaf(vv, tw.x, acc[k].x);
      acc[k].y = fmaf(vv, tw.y, acc[k].y);
    }
  }
  float2* dst = g_ft1 + ((size_t)bcx*NY + y)*NKZ;
  #pragma unroll
  for (int k = 0; k < NKZ; k++) dst[k] = acc[k];
}

// ---- forward partial DFT over Y: ft1[b,c,x,y,k] -> ft2[b,c,x,j2,k] ----
__global__ void k_fwdY(){
  __shared__ float2 sv[NY*NKZ];     // 4 KB
  __shared__ float2 stw[NK*64];     // 12 KB
  int bcx = blockIdx.x;
  for (int i = threadIdx.x; i < NY*NKZ; i += 192) sv[i] = g_ft1[(size_t)bcx*512 + i];
  for (int i = threadIdx.x; i < NK*64; i += 192) stw[i] = g_tw_yx[i];
  __syncthreads();
  int j = threadIdx.x >> 3, k = threadIdx.x & 7;
  float2 acc = make_float2(0.f, 0.f);
  for (int y = 0; y < 64; y++) cfma(acc, sv[y*8 + k], stw[j*64 + y]);
  g_ft2[(size_t)bcx*192 + threadIdx.x] = acc;
}

// ---- forward partial DFT over X: ft2[b,c,x,j2,k] -> modes[b,c,j1,j2,k] ----
__global__ void k_fwdX(){
  __shared__ float2 stw[64];
  int bc = blockIdx.x / NK, j1 = blockIdx.x % NK;
  if (threadIdx.x < 64) stw[threadIdx.x] = g_tw_yx[j1*64 + threadIdx.x];
  __syncthreads();
  const float2* src = g_ft2 + (size_t)bc*NX*192 + threadIdx.x;
  float2 acc = make_float2(0.f, 0.f);
  for (int x = 0; x < 64; x++) cfma(acc, src[(size_t)x*192], stw[x]);
  g_modes[(size_t)bc*NMODE + j1*192 + threadIdx.x] = acc;
}

// ---- channel mix per mode: out[b,o] = sum_i modes[b,i] * w[i,o] ----
__global__ void k_mix(int L){
  __shared__ float2 s_in[256];    // [b*32+i]
  __shared__ float2 s_w[1024];    // [i*32+o]
  int m = blockIdx.x;
  int tid = threadIdx.x;
  s_in[tid] = g_modes[(size_t)tid*NMODE + m];
  const float2* wt = g_wt + (size_t)L*WPL + (size_t)m*1024;
  for (int i = tid; i < 1024; i += 256) s_w[i] = wt[i];
  __syncthreads();
  int bb = tid >> 5, o = tid & 31;
  float2 acc = make_float2(0.f, 0.f);
  #pragma unroll 8
  for (int i = 0; i < 32; i++) cfma(acc, s_in[bb*32 + i], s_w[i*32 + o]);
  g_modes2[(size_t)(bb*32 + o)*NMODE + m] = acc;
}

// ---- inverse over X: modes2[b,o,j1,j2,k] -> ft2[b,o,x,j2,k] ----
__global__ void k_invX(){
  __shared__ float2 stw[NK*64];     // 12 KB
  int bo = blockIdx.x;
  int tid = threadIdx.x;            // j2*8+k, 192 threads
  for (int i = tid; i < NK*64; i += 192) stw[i] = g_tw_yx[i];
  float2 m[NK];
  #pragma unroll
  for (int j1 = 0; j1 < NK; j1++)
    m[j1] = g_modes2[(size_t)bo*NMODE + j1*192 + tid];
  __syncthreads();
  for (int x = 0; x < 64; x++){
    float2 acc = make_float2(0.f, 0.f);
    #pragma unroll
    for (int j1 = 0; j1 < NK; j1++) cfma_cj(acc, m[j1], stw[j1*64 + x]);
    g_ft2[((size_t)bo*64 + x)*192 + tid] = acc;
  }
}

// ---- inverse over Y: ft2[b,o,x,j2,k] -> ft1[b,o,x,y,k] ----
__global__ void k_invY(){
  __shared__ float2 s_in[192];      // 1.5 KB
  __shared__ float2 stw[NK*64];     // 12 KB
  int box = blockIdx.x;
  if (threadIdx.x < 192) s_in[threadIdx.x] = g_ft2[(size_t)box*192 + threadIdx.x];
  for (int i = threadIdx.x; i < NK*64; i += 256) stw[i] = g_tw_yx[i];
  __syncthreads();
  for (int o = threadIdx.x; o < 512; o += 256){
    int y = o >> 3, k = o & 7;
    float2 acc = make_float2(0.f, 0.f);
    #pragma unroll 8
    for (int j2 = 0; j2 < NK; j2++) cfma_cj(acc, s_in[j2*8 + k], stw[j2*64 + y]);
    g_ft1[(size_t)box*512 + o] = acc;
  }
}

// ---- inverse over T (+scale+Re) + conv1x1 + bias + optional gelu ----
// Register-blocked: 2 xy per block; each thread owns a 2-o x 5-t output tile.
__global__ void __launch_bounds__(256) k_invT_pw(int dir, const float* __restrict__ convw,
                          const float* __restrict__ convb, int act){
  __shared__ float  s_v[2*32*40];      // 10.0 KB (input v, reused for output)
  __shared__ float  s_w[32*33];        // padded stride to avoid o-indexed conflicts
  __shared__ float2 s_h[2*32*9];       // padded
  __shared__ float2 s_itw[NKZ*NT];
  __shared__ float  s_b[NW];
  const float* vin  = dir ? g_bufB : g_bufA;
  float*       vout = dir ? g_bufA : g_bufB;
  int gx  = blockIdx.x;                // xy-pair index
  int bb  = gx >> 11;                  // 2048 pairs per batch
  int xy0 = (gx & 2047) * 2;
  int tid = threadIdx.x;
  size_t base = (size_t)(bb*32)*XYT + (size_t)xy0*NT;    // + c*XYT

  // load v: 2 xy * 32 c * 40 t, float4-vectorized (rel offset c*XYT + m*4, m=h*10+mm)
  for (int idx = tid; idx < 640; idx += 256){
    int c = idx / 20, m = idx % 20;
    float4 v4 = *(const float4*)(vin + base + (size_t)c*XYT + m*4);
    int hh = m / 10, mm = m % 10;
    *(float4*)&s_v[hh*1280 + c*40 + mm*4] = v4;
  }
  // spectral coefficients for both xy, all o
  for (int idx = tid; idx < 512; idx += 256){
    int hh = idx >> 8, rem = idx & 255, o = rem >> 3, k = rem & 7;
    s_h[hh*288 + o*9 + k] = g_ft1[(size_t)(bb*32+o)*32768 + (size_t)(xy0+hh)*8 + k];
  }
  for (int i = tid; i < 1024; i += 256) s_w[(i>>5)*33 + (i&31)] = convw[i];
  for (int i = tid; i < NKZ*NT; i += 256) s_itw[i] = g_itw_t[i];
  if (tid < NW) s_b[tid] = convb[tid];
  __syncthreads();

  int half = tid >> 7, r = tid & 127;
  int o0 = (r >> 3) * 2, t0 = (r & 7) * 5;
  float acc0[5], acc1[5];
  {
    float b0 = s_b[o0], b1 = s_b[o0+1];
    #pragma unroll
    for (int j = 0; j < 5; j++){ acc0[j] = b0; acc1[j] = b1; }
  }
  // spectral idft-T contribution: Re(h * itw)
  {
    float2 h0[8], h1[8];
    #pragma unroll
    for (int k = 0; k < 8; k++){
      h0[k] = s_h[half*288 + o0*9 + k];
      h1[k] = s_h[half*288 + (o0+1)*9 + k];
    }
    #pragma unroll
    for (int k = 0; k < 8; k++){
      #pragma unroll
      for (int j = 0; j < 5; j++){
        float2 tw = s_itw[k*NT + t0 + j];
        acc0[j] = fmaf(h0[k].x, tw.x, fmaf(-h0[k].y, tw.y, acc0[j]));
        acc1[j] = fmaf(h1[k].x, tw.x, fmaf(-h1[k].y, tw.y, acc1[j]));
      }
    }
  }
  // conv1x1: weights in registers
  {
    float w0[32], w1[32];
    #pragma unroll
    for (int i = 0; i < 32; i++){ w0[i] = s_w[o0*33 + i]; w1[i] = s_w[(o0+1)*33 + i]; }
    const float* vh = s_v + half*1280;
    #pragma unroll 8
    for (int i = 0; i < 32; i++){
      float vj[5];
      #pragma unroll
      for (int j = 0; j < 5; j++) vj[j] = vh[i*40 + t0 + j];
      #pragma unroll
      for (int j = 0; j < 5; j++){
        acc0[j] = fmaf(w0[i], vj[j], acc0[j]);
        acc1[j] = fmaf(w1[i], vj[j], acc1[j]);
      }
    }
  }
  if (act){
    #pragma unroll
    for (int j = 0; j < 5; j++){ acc0[j] = gelu_f(acc0[j]); acc1[j] = gelu_f(acc1[j]); }
  }
  __syncthreads();           // everyone done reading s_v
  {
    float* ov = s_v + half*1280;
    #pragma unroll
    for (int j = 0; j < 5; j++){ ov[o0*40 + t0 + j] = acc0[j]; ov[(o0+1)*40 + t0 + j] = acc1[j]; }
  }
  __syncthreads();
  // coalesced float4 writeback
  for (int idx = tid; idx < 640; idx += 256){
    int c = idx / 20, m = idx % 20;
    int hh = m / 10, mm = m % 10;
    float4 v4 = *(const float4*)&s_v[hh*1280 + c*40 + mm*4];
    *(float4*)(vout + base + (size_t)c*XYT + m*4) = v4;
  }
}

// ---- head: fc1 (gelu) + fc2; v in registers, w1 broadcast from shared ----
__global__ void __launch_bounds__(256) k_head(const float* __restrict__ w1, const float* __restrict__ b1,
                       const float* __restrict__ w2, const float* __restrict__ b2,
                       float* __restrict__ out){
  __shared__ float s_w1[2048];
  __shared__ float s_b1[64];
  __shared__ float s_w2[128];
  __shared__ float s_b2[2];
  int tid = threadIdx.x;
  for (int i = tid; i < 2048; i += 256) s_w1[i] = w1[i];
  if (tid < 64)  s_b1[tid] = b1[tid];
  if (tid < 128) s_w2[tid] = w2[tid];
  if (tid < 2)   s_b2[tid] = b2[tid];
  __syncthreads();
  if (tid >= 240) return;
  int xy_l = tid / 20, tp = tid % 20;        // thread covers t=2*tp, 2*tp+1
  int g = blockIdx.x * 12 + xy_l;
  if (g >= 32768) return;
  int bb = g >> 12, xy = g & 4095;
  float2 vreg[32];
  const float* vb = g_bufB + (size_t)(bb*32)*XYT + (size_t)xy*NT + tp*2;
  #pragma unroll
  for (int c = 0; c < 32; c++) vreg[c] = *(const float2*)(vb + (size_t)c*XYT);
  float o00 = s_b2[0], o01 = s_b2[1], o10 = s_b2[0], o11 = s_b2[1];
  for (int j = 0; j < 64; j++){
    float h0 = s_b1[j], h1 = h0;
    #pragma unroll 8
    for (int c = 0; c < 32; c++){
      float w = s_w1[c*64 + j];
      h0 = fmaf(vreg[c].x, w, h0);
      h1 = fmaf(vreg[c].y, w, h1);
    }
    float g0 = gelu_f(h0), g1 = gelu_f(h1);
    float wa = s_w2[j*2], wb = s_w2[j*2 + 1];
    o00 = fmaf(g0, wa, o00); o01 = fmaf(g0, wb, o01);
    o10 = fmaf(g1, wa, o10); o11 = fmaf(g1, wb, o11);
  }
  float4 res = make_float4(o00, o01, o10, o11);
  *(float4*)(out + (size_t)g*80 + tp*4) = res;
}

static void run_layer(int L, int dir, int act, const float* convw, const float* convb){
  k_fwdT<<<NB*NW*NX, 64>>>(dir);
  k_fwdY<<<NB*NW*NX, 192>>>();
  k_fwdX<<<NB*NW*NK, 192>>>();
  k_mix<<<NMODE, 256>>>(L);
  k_invX<<<NB*NW, 192>>>();
  k_invY<<<NB*NW*NX, 256>>>();
  k_invT_pw<<<NB*2048, 256>>>(dir, convw, convb, act);
}

extern "C" void kernel_launch(void* const* d_in, const int* in_sizes, int n_in,
                              void* d_out, int out_size){
  (void)in_sizes; (void)n_in; (void)out_size;
  const float* h     = (const float*)d_in[0];
  const float* xin   = (const float*)d_in[1];
  const float* fc0_w = (const float*)d_in[2];
  const float* fc0_b = (const float*)d_in[3];
  const float* scr[3] = {(const float*)d_in[4], (const float*)d_in[6], (const float*)d_in[8]};
  const float* sci[3] = {(const float*)d_in[5], (const float*)d_in[7], (const float*)d_in[9]};
  const float* cw[3]  = {(const float*)d_in[10], (const float*)d_in[12], (const float*)d_in[14]};
  const float* cb[3]  = {(const float*)d_in[11], (const float*)d_in[13], (const float*)d_in[15]};
  const float* fc1_w = (const float*)d_in[16];
  const float* fc1_b = (const float*)d_in[17];
  const float* fc2_w = (const float*)d_in[18];
  const float* fc2_b = (const float*)d_in[19];
  float* out = (float*)d_out;

  k_init_tw<<<1, 256>>>();
  dim3 pgrid(36, 32, 4);
  for (int L = 0; L < 3; L++)
    k_prep_w_t<<<pgrid, 256>>>(scr[L], sci[L], L);
  k_fc0<<<(NB*XYT)/256, 256>>>(h, xin, fc0_w, fc0_b);

  run_layer(0, 0, 1, cw[0], cb[0]);   // A -> B, gelu
  run_layer(1, 1, 1, cw[1], cb[1]);   // B -> A, gelu
  run_layer(2, 0, 0, cw[2], cb[2]);   // A -> B, no act

  k_head<<<(32768 + 11)/12, 256>>>(fc1_w, fc1_b, fc2_w, fc2_b, out);
}